// round 5
// baseline (speedup 1.0000x reference)
#include <cuda_runtime.h>
#include <math.h>
#include <float.h>

// Problem constants (fixed by the dataset)
#define B_   256
#define N_   512
#define K_   4
#define D_   9
#define L_   32
#define NCLS 9
#define BETA 0.01f
#define CW   0.001f

#define THREADS 256   // 2 points per thread
#define NWARPS  (THREADS / 32)

__global__ __launch_bounds__(THREADS, 2)
void loss_kernel(const float* __restrict__ kine_in,
                 const float* __restrict__ class_in,
                 const float* __restrict__ kine_pr,
                 const float* __restrict__ class_pr,
                 const float* __restrict__ mu,
                 const float* __restrict__ log_var,
                 float* __restrict__ out)
{
    __shared__ float4 s_in[N_];
    __shared__ float4 s_pr[N_];
    __shared__ float  s_in2[N_];
    __shared__ float  s_pr2[N_];
    __shared__ float  s_red1[NWARPS];
    __shared__ float  s_red2[NWARPS];
    __shared__ float  s_cnt_in[NCLS];
    __shared__ float  s_cnt_pr[NCLS];

    const int b  = blockIdx.x;
    const int t  = threadIdx.x;
    const int p0 = t;            // first point this thread owns
    const int p1 = t + THREADS;  // second point

    // ---- load kine tiles to smem, precompute squared norms ----
    const float4* kin4 = (const float4*)(kine_in + (size_t)b * N_ * K_);
    const float4* kpr4 = (const float4*)(kine_pr + (size_t)b * N_ * K_);
    #pragma unroll
    for (int r = 0; r < 2; ++r) {
        int p = t + r * THREADS;
        float4 a = kin4[p];
        s_in[p]  = a;
        s_in2[p] = fmaf(a.x, a.x, fmaf(a.y, a.y, fmaf(a.z, a.z, a.w * a.w)));
        float4 q = kpr4[p];
        s_pr[p]  = q;
        s_pr2[p] = fmaf(q.x, q.x, fmaf(q.y, q.y, fmaf(q.z, q.z, q.w * q.w)));
    }
    if (t < NCLS) { s_cnt_in[t] = 0.f; s_cnt_pr[t] = 0.f; }
    __syncthreads();

    // ---- pass 1: input points p0,p1 vs all pred points ----
    float best1a = FLT_MAX, best1b = FLT_MAX;
    int   idx1a  = 0,       idx1b  = 0;
    {
        const float4 xa = s_in[p0];  const float xa2 = s_in2[p0];
        const float4 xb = s_in[p1];  const float xb2 = s_in2[p1];
        #pragma unroll 8
        for (int m = 0; m < N_; ++m) {
            float4 y  = s_pr[m];
            float  y2 = s_pr2[m];
            float xya = fmaf(xa.x, y.x, fmaf(xa.y, y.y, fmaf(xa.z, y.z, xa.w * y.w)));
            float xyb = fmaf(xb.x, y.x, fmaf(xb.y, y.y, fmaf(xb.z, y.z, xb.w * y.w)));
            float da  = fmaxf(fmaf(-2.f, xya, xa2 + y2), 0.f);
            float db  = fmaxf(fmaf(-2.f, xyb, xb2 + y2), 0.f);
            if (da < best1a) { best1a = da; idx1a = m; }
            if (db < best1b) { best1b = db; idx1b = m; }
        }
    }

    // ---- pass 2: pred points p0,p1 vs all input points ----
    float best2a = FLT_MAX, best2b = FLT_MAX;
    int   idx2a  = 0,       idx2b  = 0;
    {
        const float4 ya = s_pr[p0];  const float ya2 = s_pr2[p0];
        const float4 yb = s_pr[p1];  const float yb2 = s_pr2[p1];
        #pragma unroll 8
        for (int n = 0; n < N_; ++n) {
            float4 x  = s_in[n];
            float  x2 = s_in2[n];
            float xya = fmaf(x.x, ya.x, fmaf(x.y, ya.y, fmaf(x.z, ya.z, x.w * ya.w)));
            float xyb = fmaf(x.x, yb.x, fmaf(x.y, yb.y, fmaf(x.z, yb.z, x.w * yb.w)));
            float da  = fmaxf(fmaf(-2.f, xya, x2 + ya2), 0.f);
            float db  = fmaxf(fmaf(-2.f, xyb, x2 + yb2), 0.f);
            if (da < best2a) { best2a = da; idx2a = n; }
            if (db < best2b) { best2b = db; idx2b = n; }
        }
    }

    // ---- class data: histograms + nearest-neighbor class dots ----
    const float* cinB = class_in + (size_t)b * N_ * D_;
    const float* cprB = class_pr + (size_t)b * N_ * D_;

    float dots = 0.f;
    #pragma unroll
    for (int r = 0; r < 2; ++r) {
        const int p    = (r == 0) ? p0 : p1;
        const int i1   = (r == 0) ? idx1a : idx1b;
        const int i2   = (r == 0) ? idx2a : idx2b;

        float ci[D_], cp[D_];
        #pragma unroll
        for (int d = 0; d < D_; ++d) ci[d] = cinB[p * D_ + d];
        #pragma unroll
        for (int d = 0; d < D_; ++d) cp[d] = cprB[p * D_ + d];

        // argmax(class_input[p]) — first occurrence on ties
        {
            int li = 0; float mv = ci[0];
            #pragma unroll
            for (int d = 1; d < D_; ++d) if (ci[d] > mv) { mv = ci[d]; li = d; }
            atomicAdd(&s_cnt_in[li], 1.f);
        }
        // argmax(exp(class_pred[p])): exp is strictly monotonic and inputs are
        // ~N(0,1) (no over/underflow), so raw-logit argmax is identical.
        {
            int lp = 0; float mv = cp[0];
            #pragma unroll
            for (int d = 1; d < D_; ++d) if (cp[d] > mv) { mv = cp[d]; lp = d; }
            atomicAdd(&s_cnt_pr[lp], 1.f);
        }

        // dot(class_pred[idx1[p]], class_input[p]) + dot(class_input[idx2[p]], class_pred[p])
        const float* g1 = cprB + (size_t)i1 * D_;
        const float* g2 = cinB + (size_t)i2 * D_;
        float d1 = 0.f, d2 = 0.f;
        #pragma unroll
        for (int d = 0; d < D_; ++d) d1 = fmaf(g1[d], ci[d], d1);
        #pragma unroll
        for (int d = 0; d < D_; ++d) d2 = fmaf(g2[d], cp[d], d2);
        dots += d1 + d2;
    }

    // ---- block reduction: chamfer terms + class dots ----
    float v1 = (best1a + best1b) + (best2a + best2b);  // chamfer contribution
    float v2 = dots;                                   // class contribution (negated later)
    #pragma unroll
    for (int o = 16; o > 0; o >>= 1) {
        v1 += __shfl_down_sync(0xFFFFFFFFu, v1, o);
        v2 += __shfl_down_sync(0xFFFFFFFFu, v2, o);
    }
    const int warp = t >> 5, lane = t & 31;
    if (lane == 0) { s_red1[warp] = v1; s_red2[warp] = v2; }
    __syncthreads();   // also orders histogram atomics before final read

    if (t < 32) {
        float a1 = (t < NWARPS) ? s_red1[t] : 0.f;
        float a2 = (t < NWARPS) ? s_red2[t] : 0.f;
        // KL element for lane t (L_ == 32)
        float m_  = mu[(size_t)b * L_ + t];
        float lv_ = log_var[(size_t)b * L_ + t];
        float kv  = 1.f + lv_ - m_ * m_ - expf(lv_);
        #pragma unroll
        for (int o = 16; o > 0; o >>= 1) {
            a1 += __shfl_down_sync(0xFFFFFFFFu, a1, o);
            a2 += __shfl_down_sync(0xFFFFFFFFu, a2, o);
            kv += __shfl_down_sync(0xFFFFFFFFu, kv, o);
        }
        if (t == 0) {
            float kl = -0.5f * kv;
            float cnum = 0.f;
            cnum += 2.f   * fabsf(s_cnt_pr[0] - s_cnt_in[0]);
            #pragma unroll
            for (int c = 1; c < NCLS - 1; ++c) cnum += fabsf(s_cnt_pr[c] - s_cnt_in[c]);
            cnum += 100.f * fabsf(s_cnt_pr[NCLS - 1] - s_cnt_in[NCLS - 1]);

            float total = (1.f - BETA) * (a1 - a2 + CW * cnum) + BETA * kl;
            out[b] = total;
        }
    }
}

extern "C" void kernel_launch(void* const* d_in, const int* in_sizes, int n_in,
                              void* d_out, int out_size)
{
    const float* kine_in  = (const float*)d_in[0];
    const float* class_in = (const float*)d_in[1];
    const float* kine_pr  = (const float*)d_in[2];
    const float* class_pr = (const float*)d_in[3];
    const float* mu       = (const float*)d_in[4];
    const float* log_var  = (const float*)d_in[5];
    float* out = (float*)d_out;

    loss_kernel<<<B_, THREADS>>>(kine_in, class_in, kine_pr, class_pr, mu, log_var, out);
}

// round 8
// speedup vs baseline: 1.0640x; 1.0640x over previous
#include <cuda_runtime.h>
#include <math.h>
#include <float.h>

// Problem constants (fixed by the dataset)
#define B_   256
#define N_   512
#define K_   4
#define D_   9
#define L_   32
#define NCLS 9
#define BETA 0.01f
#define CW   0.001f

#define PTHREADS 128            // partial kernel threads
#define NPART    (B_ * 4)       // 4 partial CTAs per batch

__device__ float g_partial[NPART];

// Each CTA: one Chamfer direction (dir) for one half of the queries (half)
// of one batch (b). blockIdx.x = b*4 + dir*2 + half.
__global__ __launch_bounds__(PTHREADS, 8)
void chamfer_partial(const float* __restrict__ kine_in,
                     const float* __restrict__ class_in,
                     const float* __restrict__ kine_pr,
                     const float* __restrict__ class_pr,
                     const float* __restrict__ mu,
                     const float* __restrict__ log_var)
{
    __shared__ float4 s_nb[N_];
    __shared__ float  s_nb2[N_];
    __shared__ float  s_red1[4];
    __shared__ float  s_red2[4];
    __shared__ float  s_cnt_in[NCLS];
    __shared__ float  s_cnt_pr[NCLS];

    const int bid  = blockIdx.x;
    const int b    = bid >> 2;
    const int q    = bid & 3;
    const int dir  = q >> 1;     // 0: input->pred, 1: pred->input
    const int half = q & 1;
    const int t    = threadIdx.x;

    // queries / neighbors for this direction
    const float* kq = (dir == 0) ? kine_in : kine_pr;
    const float* kn = (dir == 0) ? kine_pr : kine_in;
    const float4* kq4 = (const float4*)(kq + (size_t)b * N_ * K_);
    const float4* kn4 = (const float4*)(kn + (size_t)b * N_ * K_);

    // ---- load neighbor tile (512 points) into smem, precompute norms ----
    #pragma unroll
    for (int r = 0; r < 4; ++r) {
        int p = t + r * PTHREADS;
        float4 v = kn4[p];
        s_nb[p]  = v;
        s_nb2[p] = fmaf(v.x, v.x, fmaf(v.y, v.y, fmaf(v.z, v.z, v.w * v.w)));
    }
    if (t < NCLS) { s_cnt_in[t] = 0.f; s_cnt_pr[t] = 0.f; }

    // ---- load this thread's 2 query points from gmem (registers only) ----
    const int p0 = half * 256 + t;
    const int p1 = p0 + PTHREADS;
    const float4 xa = kq4[p0];
    const float4 xb = kq4[p1];
    const float xa2 = fmaf(xa.x, xa.x, fmaf(xa.y, xa.y, fmaf(xa.z, xa.z, xa.w * xa.w)));
    const float xb2 = fmaf(xb.x, xb.x, fmaf(xb.y, xb.y, fmaf(xb.z, xb.z, xb.w * xb.w)));
    __syncthreads();

    // ---- min over all 512 neighbors (EXACT same arithmetic as validated kernel) ----
    float besta = FLT_MAX, bestb = FLT_MAX;
    int   idxa  = 0,       idxb  = 0;
    #pragma unroll 8
    for (int m = 0; m < N_; ++m) {
        float4 y  = s_nb[m];
        float  y2 = s_nb2[m];
        float xya = fmaf(xa.x, y.x, fmaf(xa.y, y.y, fmaf(xa.z, y.z, xa.w * y.w)));
        float xyb = fmaf(xb.x, y.x, fmaf(xb.y, y.y, fmaf(xb.z, y.z, xb.w * y.w)));
        float da  = fmaxf(fmaf(-2.f, xya, xa2 + y2), 0.f);
        float db  = fmaxf(fmaf(-2.f, xyb, xb2 + y2), 0.f);
        if (da < besta) { besta = da; idxa = m; }
        if (db < bestb) { bestb = db; idxb = m; }
    }

    // ---- class dots for this direction ----
    const float* cinB = class_in + (size_t)b * N_ * D_;
    const float* cprB = class_pr + (size_t)b * N_ * D_;
    const float* qcls = (dir == 0) ? cinB : cprB;   // class vec of the query point
    const float* ncls = (dir == 0) ? cprB : cinB;   // class vec gathered by NN index

    float dots = 0.f;
    {
        const float* ga = ncls + (size_t)idxa * D_;
        const float* qa = qcls + (size_t)p0 * D_;
        const float* gb = ncls + (size_t)idxb * D_;
        const float* qb = qcls + (size_t)p1 * D_;
        float d1 = 0.f, d2 = 0.f;
        #pragma unroll
        for (int d = 0; d < D_; ++d) d1 = fmaf(ga[d], qa[d], d1);
        #pragma unroll
        for (int d = 0; d < D_; ++d) d2 = fmaf(gb[d], qb[d], d2);
        dots = d1 + d2;
    }

    // ---- q==0 CTA also builds both histograms (512 pts x 2, 4 pts/thread) ----
    if (q == 0) {
        #pragma unroll
        for (int r = 0; r < 4; ++r) {
            int p = t + r * PTHREADS;
            // argmax(class_input[p]) — first occurrence on ties
            {
                const float* c = cinB + (size_t)p * D_;
                int li = 0; float mv = c[0];
                #pragma unroll
                for (int d = 1; d < D_; ++d) if (c[d] > mv) { mv = c[d]; li = d; }
                atomicAdd(&s_cnt_in[li], 1.f);
            }
            // argmax(exp(class_pred[p])) == raw-logit argmax (exp monotonic; validated)
            {
                const float* c = cprB + (size_t)p * D_;
                int lp = 0; float mv = c[0];
                #pragma unroll
                for (int d = 1; d < D_; ++d) if (c[d] > mv) { mv = c[d]; lp = d; }
                atomicAdd(&s_cnt_pr[lp], 1.f);
            }
        }
    }

    // ---- block reduction over 4 warps ----
    float v1 = besta + bestb;   // chamfer partial
    float v2 = dots;            // class-dot partial
    #pragma unroll
    for (int o = 16; o > 0; o >>= 1) {
        v1 += __shfl_down_sync(0xFFFFFFFFu, v1, o);
        v2 += __shfl_down_sync(0xFFFFFFFFu, v2, o);
    }
    const int warp = t >> 5, lane = t & 31;
    if (lane == 0) { s_red1[warp] = v1; s_red2[warp] = v2; }
    __syncthreads();   // also orders histogram atomics

    if (t < 32) {
        float a1 = (t < 4) ? s_red1[t] : 0.f;
        float a2 = (t < 4) ? s_red2[t] : 0.f;
        // KL term (only q==0 contributes); L_ == 32 lanes
        float kv = 0.f;
        if (q == 0) {
            float m_  = mu[(size_t)b * L_ + t];
            float lv_ = log_var[(size_t)b * L_ + t];
            kv = 1.f + lv_ - m_ * m_ - expf(lv_);
        }
        #pragma unroll
        for (int o = 16; o > 0; o >>= 1) {
            a1 += __shfl_down_sync(0xFFFFFFFFu, a1, o);
            a2 += __shfl_down_sync(0xFFFFFFFFu, a2, o);
            kv += __shfl_down_sync(0xFFFFFFFFu, kv, o);
        }
        if (t == 0) {
            float part = (1.f - BETA) * (a1 - a2);
            if (q == 0) {
                float kl = -0.5f * kv;
                float cnum = 0.f;
                cnum += 2.f   * fabsf(s_cnt_pr[0] - s_cnt_in[0]);
                #pragma unroll
                for (int c = 1; c < NCLS - 1; ++c) cnum += fabsf(s_cnt_pr[c] - s_cnt_in[c]);
                cnum += 100.f * fabsf(s_cnt_pr[NCLS - 1] - s_cnt_in[NCLS - 1]);
                part += (1.f - BETA) * CW * cnum + BETA * kl;
            }
            g_partial[bid] = part;
        }
    }
}

// Deterministic fixed-order combine: out[b] = sum of its 4 partials.
__global__ void combine_kernel(float* __restrict__ out)
{
    int b = threadIdx.x;   // 256 threads, 1 block
    float s = ((g_partial[4 * b + 0] + g_partial[4 * b + 1])
               + g_partial[4 * b + 2]) + g_partial[4 * b + 3];
    out[b] = s;
}

extern "C" void kernel_launch(void* const* d_in, const int* in_sizes, int n_in,
                              void* d_out, int out_size)
{
    const float* kine_in  = (const float*)d_in[0];
    const float* class_in = (const float*)d_in[1];
    const float* kine_pr  = (const float*)d_in[2];
    const float* class_pr = (const float*)d_in[3];
    const float* mu       = (const float*)d_in[4];
    const float* log_var  = (const float*)d_in[5];
    float* out = (float*)d_out;

    chamfer_partial<<<NPART, PTHREADS>>>(kine_in, class_in, kine_pr, class_pr, mu, log_var);
    combine_kernel<<<1, B_>>>(out);
}

// round 10
// speedup vs baseline: 1.2614x; 1.1855x over previous
#include <cuda_runtime.h>
#include <math.h>
#include <float.h>
#include <stdint.h>

// Problem constants (fixed by the dataset)
#define B_   256
#define N_   512
#define K_   4
#define D_   9
#define L_   32
#define NCLS 9
#define BETA 0.01f
#define CW   0.001f

#define PTHREADS 128            // partial kernel threads
#define NPART    (B_ * 4)       // 4 partial CTAs per batch

__device__ float    g_partial[NPART];
__device__ unsigned g_count[B_];   // zero-init; each use resets itself -> graph-replay safe

// ---- f32x2 packed helpers (Blackwell) ----
__device__ __forceinline__ uint64_t pack2(float lo, float hi) {
    uint64_t r; asm("mov.b64 %0, {%1, %2};" : "=l"(r) : "f"(lo), "f"(hi)); return r;
}
__device__ __forceinline__ void unpack2(uint64_t v, float& lo, float& hi) {
    asm("mov.b64 {%0, %1}, %2;" : "=f"(lo), "=f"(hi) : "l"(v));
}
__device__ __forceinline__ uint64_t fma2(uint64_t a, uint64_t b, uint64_t c) {
    uint64_t d; asm("fma.rn.f32x2 %0, %1, %2, %3;" : "=l"(d) : "l"(a), "l"(b), "l"(c)); return d;
}
__device__ __forceinline__ uint64_t mul2(uint64_t a, uint64_t b) {
    uint64_t d; asm("mul.rn.f32x2 %0, %1, %2;" : "=l"(d) : "l"(a), "l"(b)); return d;
}
__device__ __forceinline__ uint64_t add2(uint64_t a, uint64_t b) {
    uint64_t d; asm("add.rn.f32x2 %0, %1, %2;" : "=l"(d) : "l"(a), "l"(b)); return d;
}

// Each CTA: one Chamfer direction (dir) for one half of the queries (half)
// of one batch (b). blockIdx.x = b*4 + dir*2 + half.
__global__ __launch_bounds__(PTHREADS, 7)
void chamfer_partial(const float* __restrict__ kine_in,
                     const float* __restrict__ class_in,
                     const float* __restrict__ kine_pr,
                     const float* __restrict__ class_pr,
                     const float* __restrict__ mu,
                     const float* __restrict__ log_var,
                     float* __restrict__ out)
{
    // Neighbor tile, pair-interleaved for f32x2:
    //   s_xy[k] = (x_{2k}, x_{2k+1}, y_{2k}, y_{2k+1})  -> .x = x-pair, .y = y-pair (as u64)
    //   s_zw[k] = (z_{2k}, z_{2k+1}, w_{2k}, w_{2k+1})
    //   s_nn[k] = (n_{2k}, n_{2k+1})
    __shared__ ulonglong2 s_xy[N_ / 2];
    __shared__ ulonglong2 s_zw[N_ / 2];
    __shared__ uint64_t   s_nn[N_ / 2];
    __shared__ float      s_red1[4];
    __shared__ float      s_red2[4];
    __shared__ float      s_cnt_in[NCLS];
    __shared__ float      s_cnt_pr[NCLS];

    const int bid  = blockIdx.x;
    const int b    = bid >> 2;
    const int q    = bid & 3;
    const int dir  = q >> 1;     // 0: input->pred, 1: pred->input
    const int half = q & 1;
    const int t    = threadIdx.x;

    const float* kq = (dir == 0) ? kine_in : kine_pr;
    const float* kn = (dir == 0) ? kine_pr : kine_in;
    const float4* kq4 = (const float4*)(kq + (size_t)b * N_ * K_);
    const float4* kn4 = (const float4*)(kn + (size_t)b * N_ * K_);

    // ---- load neighbor tile into pair-interleaved smem, precompute norms ----
    {
        float* fxy = (float*)s_xy;
        float* fzw = (float*)s_zw;
        float* fnn = (float*)s_nn;
        #pragma unroll
        for (int r = 0; r < 4; ++r) {
            int p = t + r * PTHREADS;
            float4 v = kn4[p];
            int k = p >> 1, lane = p & 1;
            fxy[k * 4 + lane]     = v.x;
            fxy[k * 4 + 2 + lane] = v.y;
            fzw[k * 4 + lane]     = v.z;
            fzw[k * 4 + 2 + lane] = v.w;
            fnn[k * 2 + lane] = fmaf(v.x, v.x, fmaf(v.y, v.y, fmaf(v.z, v.z, v.w * v.w)));
        }
    }
    if (t < NCLS) { s_cnt_in[t] = 0.f; s_cnt_pr[t] = 0.f; }

    // ---- this thread's 2 query points (registers), broadcast-packed ----
    const int p0 = half * 256 + t;
    const int p1 = p0 + PTHREADS;
    const float4 xa = kq4[p0];
    const float4 xb = kq4[p1];
    const float xa2 = fmaf(xa.x, xa.x, fmaf(xa.y, xa.y, fmaf(xa.z, xa.z, xa.w * xa.w)));
    const float xb2 = fmaf(xb.x, xb.x, fmaf(xb.y, xb.y, fmaf(xb.z, xb.z, xb.w * xb.w)));

    const uint64_t ax = pack2(xa.x, xa.x), ay = pack2(xa.y, xa.y);
    const uint64_t az = pack2(xa.z, xa.z), aw = pack2(xa.w, xa.w);
    const uint64_t bx = pack2(xb.x, xb.x), by = pack2(xb.y, xb.y);
    const uint64_t bz = pack2(xb.z, xb.z), bw = pack2(xb.w, xb.w);
    const uint64_t a2 = pack2(xa2, xa2),   b2 = pack2(xb2, xb2);
    const uint64_t neg2 = pack2(-2.f, -2.f);
    __syncthreads();

    // ---- min over all 512 neighbors; per-lane arithmetic identical to validated scalar ----
    float besta_e = FLT_MAX, besta_o = FLT_MAX, bestb_e = FLT_MAX, bestb_o = FLT_MAX;
    int   ia_e = 0, ia_o = 0, ib_e = 0, ib_o = 0;
    #pragma unroll 8
    for (int k = 0; k < N_ / 2; ++k) {
        ulonglong2 pxy = s_xy[k];     // .x = x-pair, .y = y-pair
        ulonglong2 pzw = s_zw[k];     // .x = z-pair, .y = w-pair
        uint64_t   pnn = s_nn[k];     // norm pair

        // query a: xy = fmaf(x,yx, fmaf(y,yy, fmaf(z,yz, w*yw)))  (same chain per lane)
        uint64_t ta = mul2(aw, pzw.y);
        ta = fma2(az, pzw.x, ta);
        ta = fma2(ay, pxy.y, ta);
        ta = fma2(ax, pxy.x, ta);
        uint64_t da = fma2(neg2, ta, add2(a2, pnn));   // x2+y2 then fma(-2,xy,·)
        float dae, dao; unpack2(da, dae, dao);
        if (dae < besta_e) { besta_e = dae; ia_e = k; }
        if (dao < besta_o) { besta_o = dao; ia_o = k; }

        // query b
        uint64_t tb = mul2(bw, pzw.y);
        tb = fma2(bz, pzw.x, tb);
        tb = fma2(by, pxy.y, tb);
        tb = fma2(bx, pxy.x, tb);
        uint64_t db = fma2(neg2, tb, add2(b2, pnn));
        float dbe, dbo; unpack2(db, dbe, dbo);
        if (dbe < bestb_e) { bestb_e = dbe; ib_e = k; }
        if (dbo < bestb_o) { bestb_o = dbo; ib_o = k; }
    }

    // ---- cross-parity resolve (exact first-occurrence semantics) + final clamp ----
    float besta, bestb; int idxa, idxb;
    if (besta_e < besta_o)      { besta = besta_e; idxa = 2 * ia_e; }
    else if (besta_o < besta_e) { besta = besta_o; idxa = 2 * ia_o + 1; }
    else                        { besta = besta_e; idxa = (ia_e <= ia_o) ? 2 * ia_e : 2 * ia_o + 1; }
    if (bestb_e < bestb_o)      { bestb = bestb_e; idxb = 2 * ib_e; }
    else if (bestb_o < bestb_e) { bestb = bestb_o; idxb = 2 * ib_o + 1; }
    else                        { bestb = bestb_e; idxb = (ib_e <= ib_o) ? 2 * ib_e : 2 * ib_o + 1; }
    besta = fmaxf(besta, 0.f);
    bestb = fmaxf(bestb, 0.f);

    // ---- class dots for this direction ----
    const float* cinB = class_in + (size_t)b * N_ * D_;
    const float* cprB = class_pr + (size_t)b * N_ * D_;
    const float* qcls = (dir == 0) ? cinB : cprB;
    const float* ncls = (dir == 0) ? cprB : cinB;

    float dots = 0.f;
    {
        const float* ga = ncls + (size_t)idxa * D_;
        const float* qa = qcls + (size_t)p0 * D_;
        const float* gb = ncls + (size_t)idxb * D_;
        const float* qb = qcls + (size_t)p1 * D_;
        float d1 = 0.f, d2 = 0.f;
        #pragma unroll
        for (int d = 0; d < D_; ++d) d1 = fmaf(ga[d], qa[d], d1);
        #pragma unroll
        for (int d = 0; d < D_; ++d) d2 = fmaf(gb[d], qb[d], d2);
        dots = d1 + d2;
    }

    // ---- q==0 CTA also builds both histograms ----
    if (q == 0) {
        #pragma unroll
        for (int r = 0; r < 4; ++r) {
            int p = t + r * PTHREADS;
            {
                const float* c = cinB + (size_t)p * D_;
                int li = 0; float mv = c[0];
                #pragma unroll
                for (int d = 1; d < D_; ++d) if (c[d] > mv) { mv = c[d]; li = d; }
                atomicAdd(&s_cnt_in[li], 1.f);
            }
            {
                const float* c = cprB + (size_t)p * D_;   // exp monotonic -> raw-logit argmax
                int lp = 0; float mv = c[0];
                #pragma unroll
                for (int d = 1; d < D_; ++d) if (c[d] > mv) { mv = c[d]; lp = d; }
                atomicAdd(&s_cnt_pr[lp], 1.f);
            }
        }
    }

    // ---- block reduction over 4 warps ----
    float v1 = besta + bestb;
    float v2 = dots;
    #pragma unroll
    for (int o = 16; o > 0; o >>= 1) {
        v1 += __shfl_down_sync(0xFFFFFFFFu, v1, o);
        v2 += __shfl_down_sync(0xFFFFFFFFu, v2, o);
    }
    const int warp = t >> 5, lane = t & 31;
    if (lane == 0) { s_red1[warp] = v1; s_red2[warp] = v2; }
    __syncthreads();

    if (t < 32) {
        float a1 = (t < 4) ? s_red1[t] : 0.f;
        float a2s = (t < 4) ? s_red2[t] : 0.f;
        float kv = 0.f;
        if (q == 0) {
            float m_  = mu[(size_t)b * L_ + t];
            float lv_ = log_var[(size_t)b * L_ + t];
            kv = 1.f + lv_ - m_ * m_ - expf(lv_);
        }
        #pragma unroll
        for (int o = 16; o > 0; o >>= 1) {
            a1  += __shfl_down_sync(0xFFFFFFFFu, a1, o);
            a2s += __shfl_down_sync(0xFFFFFFFFu, a2s, o);
            kv  += __shfl_down_sync(0xFFFFFFFFu, kv, o);
        }
        if (t == 0) {
            float part = (1.f - BETA) * (a1 - a2s);
            if (q == 0) {
                float kl = -0.5f * kv;
                float cnum = 0.f;
                cnum += 2.f   * fabsf(s_cnt_pr[0] - s_cnt_in[0]);
                #pragma unroll
                for (int c = 1; c < NCLS - 1; ++c) cnum += fabsf(s_cnt_pr[c] - s_cnt_in[c]);
                cnum += 100.f * fabsf(s_cnt_pr[NCLS - 1] - s_cnt_in[NCLS - 1]);
                part += (1.f - BETA) * CW * cnum + BETA * kl;
            }
            g_partial[bid] = part;

            // ---- last-arrival CTA of this batch finalizes (fixed-order sum => deterministic) ----
            __threadfence();
            unsigned prev = atomicAdd(&g_count[b], 1u);
            if (prev == 3u) {
                __threadfence();
                float s = ((__ldcg(&g_partial[4 * b + 0]) + __ldcg(&g_partial[4 * b + 1]))
                           + __ldcg(&g_partial[4 * b + 2])) + __ldcg(&g_partial[4 * b + 3]);
                out[b] = s;
                g_count[b] = 0u;   // reset for next graph replay
            }
        }
    }
}

extern "C" void kernel_launch(void* const* d_in, const int* in_sizes, int n_in,
                              void* d_out, int out_size)
{
    const float* kine_in  = (const float*)d_in[0];
    const float* class_in = (const float*)d_in[1];
    const float* kine_pr  = (const float*)d_in[2];
    const float* class_pr = (const float*)d_in[3];
    const float* mu       = (const float*)d_in[4];
    const float* log_var  = (const float*)d_in[5];
    float* out = (float*)d_out;

    chamfer_partial<<<NPART, PTHREADS>>>(kine_in, class_in, kine_pr, class_pr, mu, log_var, out);
}

// round 12
// speedup vs baseline: 1.2674x; 1.0048x over previous
#include <cuda_runtime.h>
#include <math.h>
#include <float.h>
#include <stdint.h>

// Problem constants (fixed by the dataset)
#define B_   256
#define N_   512
#define K_   4
#define D_   9
#define L_   32
#define NCLS 9
#define BETA 0.01f
#define CW   0.001f

#define PTHREADS 128            // partial kernel threads
#define NPART    (B_ * 4)       // 4 partial CTAs per batch

__device__ float    g_partial[NPART];
__device__ unsigned g_count[B_];   // zero-init; each use resets itself -> graph-replay safe

// ---- f32x2 packed helpers (Blackwell) ----
__device__ __forceinline__ uint64_t pack2(float lo, float hi) {
    uint64_t r; asm("mov.b64 %0, {%1, %2};" : "=l"(r) : "f"(lo), "f"(hi)); return r;
}
__device__ __forceinline__ void unpack2(uint64_t v, float& lo, float& hi) {
    asm("mov.b64 {%0, %1}, %2;" : "=f"(lo), "=f"(hi) : "l"(v));
}
__device__ __forceinline__ uint64_t fma2(uint64_t a, uint64_t b, uint64_t c) {
    uint64_t d; asm("fma.rn.f32x2 %0, %1, %2, %3;" : "=l"(d) : "l"(a), "l"(b), "l"(c)); return d;
}
__device__ __forceinline__ uint64_t mul2(uint64_t a, uint64_t b) {
    uint64_t d; asm("mul.rn.f32x2 %0, %1, %2;" : "=l"(d) : "l"(a), "l"(b)); return d;
}
__device__ __forceinline__ uint64_t add2(uint64_t a, uint64_t b) {
    uint64_t d; asm("add.rn.f32x2 %0, %1, %2;" : "=l"(d) : "l"(a), "l"(b)); return d;
}

// Bit-identical recompute of one parity lane within the winning 8-iter block;
// returns absolute neighbor index of the FIRST element equal to target.
// (f32x2 per-lane rounding == scalar FFMA: validated empirically R8->R10.)
__device__ __forceinline__ int rescan_first(const float* __restrict__ fxy,
                                            const float* __restrict__ fzw,
                                            const float* __restrict__ fnn,
                                            int blk, int parity,
                                            float4 x, float x2, float target)
{
    #pragma unroll 1
    for (int j = 0; j < 8; ++j) {
        int k = blk * 8 + j;
        float yx = fxy[k * 4 + parity];
        float yy = fxy[k * 4 + 2 + parity];
        float yz = fzw[k * 4 + parity];
        float yw = fzw[k * 4 + 2 + parity];
        float nn = fnn[k * 2 + parity];
        // same chain as packed loop: t = w*yw; t = z*yz+t; t = y*yy+t; t = x*yx+t
        float xy = fmaf(x.x, yx, fmaf(x.y, yy, fmaf(x.z, yz, x.w * yw)));
        float d  = fmaf(-2.f, xy, x2 + nn);
        if (d == target) return 2 * k + parity;
    }
    return blk * 16 + parity;   // unreachable (target always present in its block)
}

// Each CTA: one Chamfer direction (dir) for one half of the queries (half)
// of one batch (b). blockIdx.x = b*4 + dir*2 + half.
__global__ __launch_bounds__(PTHREADS, 6)
void chamfer_partial(const float* __restrict__ kine_in,
                     const float* __restrict__ class_in,
                     const float* __restrict__ kine_pr,
                     const float* __restrict__ class_pr,
                     const float* __restrict__ mu,
                     const float* __restrict__ log_var,
                     float* __restrict__ out)
{
    // Neighbor tile, pair-interleaved for f32x2 (see loader for float layout)
    __shared__ ulonglong2 s_xy[N_ / 2];
    __shared__ ulonglong2 s_zw[N_ / 2];
    __shared__ uint64_t   s_nn[N_ / 2];
    __shared__ float      s_red1[4];
    __shared__ float      s_red2[4];
    __shared__ float      s_cnt_in[NCLS];
    __shared__ float      s_cnt_pr[NCLS];

    const int bid  = blockIdx.x;
    const int b    = bid >> 2;
    const int q    = bid & 3;
    const int dir  = q >> 1;     // 0: input->pred, 1: pred->input
    const int half = q & 1;
    const int t    = threadIdx.x;

    const float* kq = (dir == 0) ? kine_in : kine_pr;
    const float* kn = (dir == 0) ? kine_pr : kine_in;
    const float4* kq4 = (const float4*)(kq + (size_t)b * N_ * K_);
    const float4* kn4 = (const float4*)(kn + (size_t)b * N_ * K_);

    float* fxy = (float*)s_xy;
    float* fzw = (float*)s_zw;
    float* fnn = (float*)s_nn;

    // ---- load neighbor tile into pair-interleaved smem, precompute norms ----
    #pragma unroll
    for (int r = 0; r < 4; ++r) {
        int p = t + r * PTHREADS;
        float4 v = kn4[p];
        int k = p >> 1, lane = p & 1;
        fxy[k * 4 + lane]     = v.x;
        fxy[k * 4 + 2 + lane] = v.y;
        fzw[k * 4 + lane]     = v.z;
        fzw[k * 4 + 2 + lane] = v.w;
        fnn[k * 2 + lane] = fmaf(v.x, v.x, fmaf(v.y, v.y, fmaf(v.z, v.z, v.w * v.w)));
    }
    if (t < NCLS) { s_cnt_in[t] = 0.f; s_cnt_pr[t] = 0.f; }

    // ---- this thread's 2 query points (registers), broadcast-packed ----
    const int p0 = half * 256 + t;
    const int p1 = p0 + PTHREADS;
    const float4 xa = kq4[p0];
    const float4 xb = kq4[p1];
    const float xa2 = fmaf(xa.x, xa.x, fmaf(xa.y, xa.y, fmaf(xa.z, xa.z, xa.w * xa.w)));
    const float xb2 = fmaf(xb.x, xb.x, fmaf(xb.y, xb.y, fmaf(xb.z, xb.z, xb.w * xb.w)));

    const uint64_t ax = pack2(xa.x, xa.x), ay = pack2(xa.y, xa.y);
    const uint64_t az = pack2(xa.z, xa.z), aw = pack2(xa.w, xa.w);
    const uint64_t bx = pack2(xb.x, xb.x), by = pack2(xb.y, xb.y);
    const uint64_t bz = pack2(xb.z, xb.z), bw = pack2(xb.w, xb.w);
    const uint64_t a2 = pack2(xa2, xa2),   b2 = pack2(xb2, xb2);
    const uint64_t neg2 = pack2(-2.f, -2.f);
    __syncthreads();

    // ---- blocked min: values only via fminf; index deferred to block-id + rescan ----
    float gbae = FLT_MAX, gbao = FLT_MAX, gbbe = FLT_MAX, gbbo = FLT_MAX;
    int   blka_e = 0, blka_o = 0, blkb_e = 0, blkb_o = 0;

    #pragma unroll 1
    for (int blk = 0; blk < (N_ / 2) / 8; ++blk) {
        float bae = FLT_MAX, bao = FLT_MAX, bbe = FLT_MAX, bbo = FLT_MAX;
        #pragma unroll
        for (int j = 0; j < 8; ++j) {
            int k = blk * 8 + j;
            ulonglong2 pxy = s_xy[k];
            ulonglong2 pzw = s_zw[k];
            uint64_t   pnn = s_nn[k];

            uint64_t ta = mul2(aw, pzw.y);
            ta = fma2(az, pzw.x, ta);
            ta = fma2(ay, pxy.y, ta);
            ta = fma2(ax, pxy.x, ta);
            uint64_t da = fma2(neg2, ta, add2(a2, pnn));
            float dae, dao; unpack2(da, dae, dao);
            bae = fminf(bae, dae);
            bao = fminf(bao, dao);

            uint64_t tb = mul2(bw, pzw.y);
            tb = fma2(bz, pzw.x, tb);
            tb = fma2(by, pxy.y, tb);
            tb = fma2(bx, pxy.x, tb);
            uint64_t db = fma2(neg2, tb, add2(b2, pnn));
            float dbe, dbo; unpack2(db, dbe, dbo);
            bbe = fminf(bbe, dbe);
            bbo = fminf(bbo, dbo);
        }
        // strict < : earliest block holding the global min wins
        if (bae < gbae) { gbae = bae; blka_e = blk; }
        if (bao < gbao) { gbao = bao; blka_o = blk; }
        if (bbe < gbbe) { gbbe = bbe; blkb_e = blk; }
        if (bbo < gbbo) { gbbo = bbo; blkb_o = blk; }
    }

    // ---- recover first-occurrence indices (rescan winning blocks only) ----
    float besta, bestb; int idxa, idxb;
    if (gbae < gbao) {
        besta = gbae; idxa = rescan_first(fxy, fzw, fnn, blka_e, 0, xa, xa2, gbae);
    } else if (gbao < gbae) {
        besta = gbao; idxa = rescan_first(fxy, fzw, fnn, blka_o, 1, xa, xa2, gbao);
    } else {
        besta = gbae;
        int ie = rescan_first(fxy, fzw, fnn, blka_e, 0, xa, xa2, gbae);
        int io = rescan_first(fxy, fzw, fnn, blka_o, 1, xa, xa2, gbao);
        idxa = min(ie, io);
    }
    if (gbbe < gbbo) {
        bestb = gbbe; idxb = rescan_first(fxy, fzw, fnn, blkb_e, 0, xb, xb2, gbbe);
    } else if (gbbo < gbbe) {
        bestb = gbbo; idxb = rescan_first(fxy, fzw, fnn, blkb_o, 1, xb, xb2, gbbo);
    } else {
        bestb = gbbe;
        int ie = rescan_first(fxy, fzw, fnn, blkb_e, 0, xb, xb2, gbbe);
        int io = rescan_first(fxy, fzw, fnn, blkb_o, 1, xb, xb2, gbbo);
        idxb = min(ie, io);
    }
    besta = fmaxf(besta, 0.f);
    bestb = fmaxf(bestb, 0.f);

    // ---- class dots for this direction ----
    const float* cinB = class_in + (size_t)b * N_ * D_;
    const float* cprB = class_pr + (size_t)b * N_ * D_;
    const float* qcls = (dir == 0) ? cinB : cprB;
    const float* ncls = (dir == 0) ? cprB : cinB;

    float dots = 0.f;
    {
        const float* ga = ncls + (size_t)idxa * D_;
        const float* qa = qcls + (size_t)p0 * D_;
        const float* gb = ncls + (size_t)idxb * D_;
        const float* qb = qcls + (size_t)p1 * D_;
        float d1 = 0.f, d2 = 0.f;
        #pragma unroll
        for (int d = 0; d < D_; ++d) d1 = fmaf(ga[d], qa[d], d1);
        #pragma unroll
        for (int d = 0; d < D_; ++d) d2 = fmaf(gb[d], qb[d], d2);
        dots = d1 + d2;
    }

    // ---- q==0 CTA also builds both histograms ----
    if (q == 0) {
        #pragma unroll
        for (int r = 0; r < 4; ++r) {
            int p = t + r * PTHREADS;
            {
                const float* c = cinB + (size_t)p * D_;
                int li = 0; float mv = c[0];
                #pragma unroll
                for (int d = 1; d < D_; ++d) if (c[d] > mv) { mv = c[d]; li = d; }
                atomicAdd(&s_cnt_in[li], 1.f);
            }
            {
                const float* c = cprB + (size_t)p * D_;   // exp monotonic -> raw-logit argmax
                int lp = 0; float mv = c[0];
                #pragma unroll
                for (int d = 1; d < D_; ++d) if (c[d] > mv) { mv = c[d]; lp = d; }
                atomicAdd(&s_cnt_pr[lp], 1.f);
            }
        }
    }

    // ---- block reduction over 4 warps ----
    float v1 = besta + bestb;
    float v2 = dots;
    #pragma unroll
    for (int o = 16; o > 0; o >>= 1) {
        v1 += __shfl_down_sync(0xFFFFFFFFu, v1, o);
        v2 += __shfl_down_sync(0xFFFFFFFFu, v2, o);
    }
    const int warp = t >> 5, lane = t & 31;
    if (lane == 0) { s_red1[warp] = v1; s_red2[warp] = v2; }
    __syncthreads();

    if (t < 32) {
        float a1 = (t < 4) ? s_red1[t] : 0.f;
        float a2s = (t < 4) ? s_red2[t] : 0.f;
        float kv = 0.f;
        if (q == 0) {
            float m_  = mu[(size_t)b * L_ + t];
            float lv_ = log_var[(size_t)b * L_ + t];
            kv = 1.f + lv_ - m_ * m_ - expf(lv_);
        }
        #pragma unroll
        for (int o = 16; o > 0; o >>= 1) {
            a1  += __shfl_down_sync(0xFFFFFFFFu, a1, o);
            a2s += __shfl_down_sync(0xFFFFFFFFu, a2s, o);
            kv  += __shfl_down_sync(0xFFFFFFFFu, kv, o);
        }
        if (t == 0) {
            float part = (1.f - BETA) * (a1 - a2s);
            if (q == 0) {
                float kl = -0.5f * kv;
                float cnum = 0.f;
                cnum += 2.f   * fabsf(s_cnt_pr[0] - s_cnt_in[0]);
                #pragma unroll
                for (int c = 1; c < NCLS - 1; ++c) cnum += fabsf(s_cnt_pr[c] - s_cnt_in[c]);
                cnum += 100.f * fabsf(s_cnt_pr[NCLS - 1] - s_cnt_in[NCLS - 1]);
                part += (1.f - BETA) * CW * cnum + BETA * kl;
            }
            g_partial[bid] = part;

            // ---- last-arrival CTA of this batch finalizes (fixed-order sum => deterministic) ----
            __threadfence();
            unsigned prev = atomicAdd(&g_count[b], 1u);
            if (prev == 3u) {
                __threadfence();
                float s = ((__ldcg(&g_partial[4 * b + 0]) + __ldcg(&g_partial[4 * b + 1]))
                           + __ldcg(&g_partial[4 * b + 2])) + __ldcg(&g_partial[4 * b + 3]);
                out[b] = s;
                g_count[b] = 0u;   // reset for next graph replay
            }
        }
    }
}

extern "C" void kernel_launch(void* const* d_in, const int* in_sizes, int n_in,
                              void* d_out, int out_size)
{
    const float* kine_in  = (const float*)d_in[0];
    const float* class_in = (const float*)d_in[1];
    const float* kine_pr  = (const float*)d_in[2];
    const float* class_pr = (const float*)d_in[3];
    const float* mu       = (const float*)d_in[4];
    const float* log_var  = (const float*)d_in[5];
    float* out = (float*)d_out;

    chamfer_partial<<<NPART, PTHREADS>>>(kine_in, class_in, kine_pr, class_pr, mu, log_var, out);
}